// round 2
// baseline (speedup 1.0000x reference)
#include <cuda_runtime.h>
#include <cstdint>
#include <cstddef>

#define N_FEAT 3072
#define K_LAT  128
#define BATCH  8192
#define ROWS_PB 16
#define PAIRS   8

// scratch (no allocations allowed)
__device__ float g_M[K_LAT * K_LAT];
__device__ float g_Minv[K_LAT * K_LAT];
__device__ float g_consts[2];   // [0] = n*log2pi + logdetC, [1] = 1/sigma^2

// ---------------- packed f32x2 helpers (sm_103a) ----------------
static __device__ __forceinline__ unsigned long long pk2(float x, float y) {
    unsigned long long r;
    asm("mov.b64 %0, {%1,%2};" : "=l"(r) : "f"(x), "f"(y));
    return r;
}
static __device__ __forceinline__ float2 upk2(unsigned long long v) {
    float2 r;
    asm("mov.b64 {%0,%1}, %2;" : "=f"(r.x), "=f"(r.y) : "l"(v));
    return r;
}
static __device__ __forceinline__ unsigned long long ffma2(
    unsigned long long a, unsigned long long b, unsigned long long c) {
    unsigned long long d;
    asm("fma.rn.f32x2 %0, %1, %2, %3;" : "=l"(d) : "l"(a), "l"(b), "l"(c));
    return d;
}

// ---------------- Kernel A: M = W^T W + sigma^2 I  (128x128) ----------------
__global__ __launch_bounds__(256) void k_gram(const float* __restrict__ W,
                                              const float* __restrict__ log_var) {
    int idx = blockIdx.x * blockDim.x + threadIdx.x;   // 0..16383
    int i = idx >> 7;
    int j = idx & 127;
    const float* wi = W + i;
    const float* wj = W + j;
    float acc = 0.f;
#pragma unroll 8
    for (int r = 0; r < N_FEAT; r++) {
        acc = fmaf(wi[(size_t)r * K_LAT], wj[(size_t)r * K_LAT], acc);
    }
    if (i == j) acc += expf(log_var[0]);
    g_M[idx] = acc;
}

// ---------------- Kernel B: in-place Gauss-Jordan inverse of M ----------------
// One block, 1024 threads. Thread (i, c) owns A[i][16c .. 16c+15] in registers.
// Per step k: publish old row k + old column k to smem (double-buffered, one
// barrier per step), then every thread updates its 16 registers.
// Also accumulates logdet(M) = sum log(pivot) and writes the scalar constants.
__global__ __launch_bounds__(1024, 1) void k_invert(const float* __restrict__ log_var) {
    const int tid = threadIdx.x;
    const int i = tid & 127;     // row
    const int c = tid >> 7;      // column block 0..7 (16 cols each)

    float a[16];
    {
        const float4* mv = reinterpret_cast<const float4*>(g_M + i * K_LAT + 16 * c);
#pragma unroll
        for (int q = 0; q < 4; q++) {
            float4 v = mv[q];
            a[4 * q + 0] = v.x; a[4 * q + 1] = v.y;
            a[4 * q + 2] = v.z; a[4 * q + 3] = v.w;
        }
    }

    __shared__ __align__(16) float rowbuf[2][128];
    __shared__ float colbuf[2][128];
    float logdet = 0.f;
    int buf = 0;

    for (int k = 0; k < 128; k++) {
        // publish OLD row k and OLD column k
        if (i == k) {
            float4* rb = reinterpret_cast<float4*>(&rowbuf[buf][16 * c]);
#pragma unroll
            for (int q = 0; q < 4; q++)
                rb[q] = make_float4(a[4 * q], a[4 * q + 1], a[4 * q + 2], a[4 * q + 3]);
        }
        if (c == (k >> 4)) {
            float av = 0.f;
#pragma unroll
            for (int u = 0; u < 16; u++)
                if (u == (k & 15)) av = a[u];
            colbuf[buf][i] = av;
        }
        __syncthreads();

        float p = colbuf[buf][k];        // pivot = old A[k][k]
        float d = 1.0f / p;
        if (tid == 0) logdet += logf(p);

        if (i == k) {
#pragma unroll
            for (int u = 0; u < 16; u++) {
                int j = 16 * c + u;
                a[u] = (j == k) ? d : a[u] * d;
            }
        } else {
            float nci = -colbuf[buf][i] * d;   // new A[i][k]
            const float4* rb = reinterpret_cast<const float4*>(&rowbuf[buf][16 * c]);
#pragma unroll
            for (int q = 0; q < 4; q++) {
                float4 rv = rb[q];
                float rr[4] = {rv.x, rv.y, rv.z, rv.w};
#pragma unroll
                for (int t = 0; t < 4; t++) {
                    int u = 4 * q + t;
                    int j = 16 * c + u;
                    a[u] = (j == k) ? nci : fmaf(nci, rr[t], a[u]);
                }
            }
        }
        buf ^= 1;
    }

    {
        float4* ov = reinterpret_cast<float4*>(g_Minv + i * K_LAT + 16 * c);
#pragma unroll
        for (int q = 0; q < 4; q++)
            ov[q] = make_float4(a[4 * q], a[4 * q + 1], a[4 * q + 2], a[4 * q + 3]);
    }
    if (tid == 0) {
        const float LOG2PI = 1.8378770664093453f;
        float lv = log_var[0];
        g_consts[0] = (float)N_FEAT * LOG2PI + (float)(N_FEAT - K_LAT) * lv + logdet;
        g_consts[1] = expf(-lv);   // 1/sigma^2
    }
}

// ---------------- Kernel C: main pass ----------------
// Per block: 16 batch rows (8 f32x2 pairs), 128 threads (thread = latent col j).
//   y[p][j] = sum_r res[p][r] * W[r][j]   (res tiled through smem, packed x2)
//   ssq[p]  = sum_r res[p][r]^2
//   quad2   = y^T Minv y  (thread j computes y_j * (Minv y)_j, block-reduce)
//   out     = -0.5 * (const + (ssq - quad2)/sigma^2)
__global__ __launch_bounds__(128) void k_main(const float* __restrict__ ex,
                                              const float* __restrict__ W,
                                              const float* __restrict__ mean,
                                              float* __restrict__ out) {
    const int tid = threadIdx.x;
    const int base = blockIdx.x * ROWS_PB;

    __shared__ __align__(16) unsigned long long resS[PAIRS][128];
    __shared__ float2 redT[4][PAIRS];
    __shared__ float2 redS[4][PAIRS];

    unsigned long long acc[PAIRS];
    unsigned long long ssq[PAIRS];
#pragma unroll
    for (int p = 0; p < PAIRS; p++) { acc[p] = 0ull; ssq[p] = 0ull; }

    for (int r0 = 0; r0 < N_FEAT; r0 += 128) {
        float m = mean[r0 + tid];
#pragma unroll
        for (int p = 0; p < PAIRS; p++) {
            float x0 = ex[(size_t)(base + 2 * p)     * N_FEAT + r0 + tid] - m;
            float x1 = ex[(size_t)(base + 2 * p + 1) * N_FEAT + r0 + tid] - m;
            unsigned long long v = pk2(x0, x1);
            ssq[p] = ffma2(v, v, ssq[p]);
            resS[p][tid] = v;
        }
        __syncthreads();

        const float* Wc = W + (size_t)r0 * K_LAT + tid;
#pragma unroll 4
        for (int rr = 0; rr < 128; rr += 2) {
            float w0 = Wc[(size_t)rr * K_LAT];
            float w1 = Wc[(size_t)(rr + 1) * K_LAT];
            unsigned long long w20 = pk2(w0, w0);
            unsigned long long w21 = pk2(w1, w1);
#pragma unroll
            for (int p = 0; p < PAIRS; p++) {
                ulonglong2 v = *reinterpret_cast<const ulonglong2*>(&resS[p][rr]);
                acc[p] = ffma2(v.x, w20, acc[p]);
                acc[p] = ffma2(v.y, w21, acc[p]);
            }
        }
        __syncthreads();
    }

    // stage y in smem for the quadratic form
#pragma unroll
    for (int p = 0; p < PAIRS; p++) resS[p][tid] = acc[p];
    __syncthreads();

    const float* Mrow = g_Minv + tid * K_LAT;
    unsigned long long qv[PAIRS];
#pragma unroll
    for (int p = 0; p < PAIRS; p++) qv[p] = 0ull;
#pragma unroll 4
    for (int j = 0; j < 128; j += 2) {
        float2 m2 = *reinterpret_cast<const float2*>(Mrow + j);
        unsigned long long m20 = pk2(m2.x, m2.x);
        unsigned long long m21 = pk2(m2.y, m2.y);
#pragma unroll
        for (int p = 0; p < PAIRS; p++) {
            ulonglong2 v = *reinterpret_cast<const ulonglong2*>(&resS[p][j]);
            qv[p] = ffma2(v.x, m20, qv[p]);
            qv[p] = ffma2(v.y, m21, qv[p]);
        }
    }

    float2 tv[PAIRS], sv[PAIRS];
#pragma unroll
    for (int p = 0; p < PAIRS; p++) {
        float2 y2 = upk2(acc[p]);
        float2 q2 = upk2(qv[p]);
        tv[p] = make_float2(y2.x * q2.x, y2.y * q2.y);
        sv[p] = upk2(ssq[p]);
    }
#pragma unroll
    for (int off = 16; off > 0; off >>= 1) {
#pragma unroll
        for (int p = 0; p < PAIRS; p++) {
            tv[p].x += __shfl_xor_sync(0xffffffffu, tv[p].x, off);
            tv[p].y += __shfl_xor_sync(0xffffffffu, tv[p].y, off);
            sv[p].x += __shfl_xor_sync(0xffffffffu, sv[p].x, off);
            sv[p].y += __shfl_xor_sync(0xffffffffu, sv[p].y, off);
        }
    }
    int warp = tid >> 5, lane = tid & 31;
    if (lane == 0) {
#pragma unroll
        for (int p = 0; p < PAIRS; p++) { redT[warp][p] = tv[p]; redS[warp][p] = sv[p]; }
    }
    __syncthreads();
    if (tid < PAIRS) {
        float2 T = make_float2(0.f, 0.f), S = make_float2(0.f, 0.f);
#pragma unroll
        for (int w = 0; w < 4; w++) {
            T.x += redT[w][tid].x; T.y += redT[w][tid].y;
            S.x += redS[w][tid].x; S.y += redS[w][tid].y;
        }
        float cst = g_consts[0];
        float is2 = g_consts[1];
        out[base + 2 * tid]     = -0.5f * (cst + (S.x - T.x) * is2);
        out[base + 2 * tid + 1] = -0.5f * (cst + (S.y - T.y) * is2);
    }
}

// ---------------- launch ----------------
extern "C" void kernel_launch(void* const* d_in, const int* in_sizes, int n_in,
                              void* d_out, int out_size) {
    // identify inputs by element count (robust to metadata ordering)
    const float* ex = nullptr;
    const float* W = nullptr;
    const float* lv = nullptr;
    const float* mean = nullptr;
    for (int t = 0; t < n_in; t++) {
        if (in_sizes[t] == BATCH * N_FEAT)      ex   = (const float*)d_in[t];
        else if (in_sizes[t] == N_FEAT * K_LAT) W    = (const float*)d_in[t];
        else if (in_sizes[t] == N_FEAT)         mean = (const float*)d_in[t];
        else if (in_sizes[t] == 1)              lv   = (const float*)d_in[t];
    }
    float* out = (float*)d_out;

    k_gram<<<(K_LAT * K_LAT) / 256, 256>>>(W, lv);
    k_invert<<<1, 1024>>>(lv);
    k_main<<<BATCH / ROWS_PB, 128>>>(ex, W, mean, out);
}

// round 8
// speedup vs baseline: 1.7223x; 1.7223x over previous
#include <cuda_runtime.h>
#include <cuda_bf16.h>
#include <cstdint>
#include <cstddef>

#define N_FEAT 3072
#define K_LAT  128
#define BATCH  8192
#define CH     64
#define NCH    48          /* 3072 / 64 */
#define MBLK   64
#define NBLOCKS (BATCH / MBLK)

// ---------------- device scratch (static — no allocations) ----------------
__device__ float g_Mpart[NCH * K_LAT * K_LAT];                      // 3 MB gram partials
__device__ float g_consts[2];                                       // [0]=n log2pi+logdetC, [1]=1/sigma^2
__device__ __align__(16) __nv_bfloat16 g_Wt_sw[NCH * K_LAT * CH];   // 768 KB, per-chunk SW128 W^T
__device__ __align__(16) __nv_bfloat16 g_Minv_bf[K_LAT * K_LAT];    // 32 KB, row-major bf16 Minv

#define SWZ(o) ((o) ^ (((o) >> 3) & 0x70))

static __device__ __forceinline__ uint32_t smem_u32(const void* p) {
    uint32_t a;
    asm("{ .reg .u64 t; cvta.to.shared.u64 t, %1; cvt.u32.u64 %0, t; }" : "=r"(a) : "l"(p));
    return a;
}

#define LDMX4(r, addr) \
    asm volatile("ldmatrix.sync.aligned.m8n8.x4.shared.b16 {%0,%1,%2,%3}, [%4];" \
        : "=r"((r)[0]), "=r"((r)[1]), "=r"((r)[2]), "=r"((r)[3]) : "r"(addr))

#define MMA16816(d, a, b0, b1) \
    asm volatile("mma.sync.aligned.m16n8k16.row.col.f32.bf16.bf16.f32 " \
        "{%0,%1,%2,%3}, {%4,%5,%6,%7}, {%8,%9}, {%0,%1,%2,%3};" \
        : "+f"((d)[0]), "+f"((d)[1]), "+f"((d)[2]), "+f"((d)[3]) \
        : "r"((a)[0]), "r"((a)[1]), "r"((a)[2]), "r"((a)[3]), "r"(b0), "r"(b1))

static __device__ __forceinline__ uint32_t bfx2(float a, float b) {
    __nv_bfloat162 h = __floats2bfloat162_rn(a, b);
    return *reinterpret_cast<uint32_t*>(&h);
}
static __device__ __forceinline__ float2 ubfx2(uint32_t v) {
    float2 r;
    r.x = __uint_as_float(v << 16);
    r.y = __uint_as_float(v & 0xffff0000u);
    return r;
}

// ---------------- k_prep: build per-chunk SW128 bf16 W^T  ([n=128 rows][k=64 cols]) ----------------
__global__ __launch_bounds__(256) void k_prep(const float* __restrict__ W) {
    __shared__ __align__(16) unsigned char sbuf[K_LAT * CH * 2];   // 16 KB
    int c = blockIdx.x, t = threadIdx.x;
#pragma unroll 4
    for (int it = 0; it < 32; it++) {
        int l = it * 256 + t;          // 0..8191
        int rr = l >> 7;               // k within chunk
        int n  = l & 127;              // latent index
        float v = W[(size_t)(c * CH + rr) * K_LAT + n];
        unsigned off = SWZ((unsigned)(n * 128 + rr * 2));
        *reinterpret_cast<__nv_bfloat16*>(sbuf + off) = __float2bfloat16(v);
    }
    __syncthreads();
    const uint4* s4 = reinterpret_cast<const uint4*>(sbuf);
    uint4* d4 = reinterpret_cast<uint4*>(g_Wt_sw) + c * 1024;
#pragma unroll
    for (int i = 0; i < 4; i++) d4[i * 256 + t] = s4[i * 256 + t];
}

// ---------------- k_gram2: deterministic partial grams (fp32) ----------------
__global__ __launch_bounds__(256) void k_gram2(const float* __restrict__ W) {
    __shared__ __align__(16) float Ws[CH][K_LAT];   // 32 KB
    int c = blockIdx.x, t = threadIdx.x;
#pragma unroll 4
    for (int it = 0; it < 32; it++) {
        int l = it * 256 + t;
        Ws[l >> 7][l & 127] = W[(size_t)(c * CH + (l >> 7)) * K_LAT + (l & 127)];
    }
    __syncthreads();
    int i0 = (t >> 4) * 8, j0 = (t & 15) * 8;
    float acc[8][8];
#pragma unroll
    for (int a = 0; a < 8; a++)
#pragma unroll
        for (int b = 0; b < 8; b++) acc[a][b] = 0.f;
#pragma unroll 4
    for (int rr = 0; rr < CH; rr++) {
        float4 wi0 = *(const float4*)&Ws[rr][i0];
        float4 wi1 = *(const float4*)&Ws[rr][i0 + 4];
        float4 wj0 = *(const float4*)&Ws[rr][j0];
        float4 wj1 = *(const float4*)&Ws[rr][j0 + 4];
        float wi[8] = {wi0.x, wi0.y, wi0.z, wi0.w, wi1.x, wi1.y, wi1.z, wi1.w};
        float wj[8] = {wj0.x, wj0.y, wj0.z, wj0.w, wj1.x, wj1.y, wj1.z, wj1.w};
#pragma unroll
        for (int a = 0; a < 8; a++)
#pragma unroll
            for (int b = 0; b < 8; b++) acc[a][b] = fmaf(wi[a], wj[b], acc[a][b]);
    }
    float* outp = g_Mpart + (size_t)c * (K_LAT * K_LAT);
#pragma unroll
    for (int a = 0; a < 8; a++) {
        float4* o4 = reinterpret_cast<float4*>(outp + (i0 + a) * K_LAT + j0);
        o4[0] = make_float4(acc[a][0], acc[a][1], acc[a][2], acc[a][3]);
        o4[1] = make_float4(acc[a][4], acc[a][5], acc[a][6], acc[a][7]);
    }
}

// ---------------- k_invert: reduce partials, GJ inverse, emit bf16 Minv ----------------
__global__ __launch_bounds__(1024, 1) void k_invert(const float* __restrict__ log_var) {
    const int tid = threadIdx.x;
    const int i = tid & 127;
    const int c = tid >> 7;
    float lv = log_var[0];
    float sig2 = expf(lv);

    float a[16];
#pragma unroll
    for (int u = 0; u < 16; u++) a[u] = 0.f;
    {
        const float* base = g_Mpart + i * K_LAT + 16 * c;
#pragma unroll 4
        for (int p = 0; p < NCH; p++) {
            const float4* mv = reinterpret_cast<const float4*>(base + (size_t)p * (K_LAT * K_LAT));
#pragma unroll
            for (int q = 0; q < 4; q++) {
                float4 v = mv[q];
                a[4 * q + 0] += v.x; a[4 * q + 1] += v.y;
                a[4 * q + 2] += v.z; a[4 * q + 3] += v.w;
            }
        }
    }
#pragma unroll
    for (int u = 0; u < 16; u++)
        if (16 * c + u == i) a[u] += sig2;

    __shared__ __align__(16) float rowbuf[2][128];
    __shared__ float colbuf[2][128];
    float logdet = 0.f;
    int buf = 0;

    for (int k = 0; k < 128; k++) {
        if (i == k) {
            float4* rb = reinterpret_cast<float4*>(&rowbuf[buf][16 * c]);
#pragma unroll
            for (int q = 0; q < 4; q++)
                rb[q] = make_float4(a[4 * q], a[4 * q + 1], a[4 * q + 2], a[4 * q + 3]);
        }
        if (c == (k >> 4)) {
            float av = 0.f;
#pragma unroll
            for (int u = 0; u < 16; u++)
                if (u == (k & 15)) av = a[u];
            colbuf[buf][i] = av;
        }
        __syncthreads();

        float p = colbuf[buf][k];
        float d = 1.0f / p;
        if (tid == 0) logdet += logf(p);

        if (i == k) {
#pragma unroll
            for (int u = 0; u < 16; u++) {
                int j = 16 * c + u;
                a[u] = (j == k) ? d : a[u] * d;
            }
        } else {
            float nci = -colbuf[buf][i] * d;
            const float4* rb = reinterpret_cast<const float4*>(&rowbuf[buf][16 * c]);
#pragma unroll
            for (int q = 0; q < 4; q++) {
                float4 rv = rb[q];
                float rr[4] = {rv.x, rv.y, rv.z, rv.w};
#pragma unroll
                for (int tq = 0; tq < 4; tq++) {
                    int u = 4 * q + tq;
                    int j = 16 * c + u;
                    a[u] = (j == k) ? nci : fmaf(nci, rr[tq], a[u]);
                }
            }
        }
        buf ^= 1;
    }

    // emit bf16 Minv, plain row-major [128][128]
    {
        uint32_t* dst = reinterpret_cast<uint32_t*>(g_Minv_bf) + (i * K_LAT + 16 * c) / 2;
#pragma unroll
        for (int u = 0; u < 16; u += 2)
            dst[u / 2] = bfx2(a[u], a[u + 1]);
    }
    if (tid == 0) {
        const float LOG2PI = 1.8378770664093453f;
        g_consts[0] = (float)N_FEAT * LOG2PI + (float)(N_FEAT - K_LAT) * lv + logdet;
        g_consts[1] = expf(-lv);
    }
}

// ---------------- k_main: mma.sync bf16 pipeline ----------------
// mainloop smem:  A 2x8KB @0, B 2x16KB @16384, mean 12KB @49152, red @61440
// epilogue smem:  Y (pitch 272B, 64 rows) @0, Minv (pitch 272B, 128 rows) @17408
#define SM_A     0
#define SM_B     16384
#define SM_MEAN  49152
#define SM_RED   61440
#define SM_Y     0
#define SM_MI    17408
#define SM_TOTAL 62720

__global__ void __launch_bounds__(256, 2) k_main(const float* __restrict__ ex,
                                                 const float* __restrict__ mean,
                                                 float* __restrict__ out) {
    extern __shared__ __align__(16) unsigned char smem[];
    uint32_t sb = smem_u32(smem);
    const int t = threadIdx.x, lane = t & 31, wid = t >> 5;
    const int wm = wid & 1, wn = wid >> 1;        // warp grid: 2 (M) x 4 (N)
    const int m0 = wm * 32, n0 = wn * 32;

    // cache mean in smem
    float* meanS = reinterpret_cast<float*>(smem + SM_MEAN);
    for (int i = t; i < N_FEAT; i += 256) meanS[i] = mean[i];

    // residual load geometry: 4 threads per row, 16 cols each
    const int row = t >> 2, q = t & 3;
    const float4* exp4 =
        reinterpret_cast<const float4*>(ex + (size_t)(blockIdx.x * MBLK + row) * N_FEAT) + q * 4;
    float4 cur[4];
#pragma unroll
    for (int g = 0; g < 4; g++) cur[g] = exp4[g];

    // ldmatrix lane geometry (SW128, 128B rows)
    const int rA = lane & 15, cA16 = lane >> 4;
    uint32_t aOff[2], aXor[2];
#pragma unroll
    for (int mi = 0; mi < 2; mi++) {
        int r = m0 + mi * 16 + rA;
        aOff[mi] = (uint32_t)(r * 128);
        aXor[mi] = (uint32_t)((r & 7) << 4);
    }
    const uint32_t aCol = (uint32_t)(cA16 * 16);
    const int nB = (lane & 7) + ((lane & 16) ? 8 : 0);
    uint32_t bOff[2];
#pragma unroll
    for (int nj = 0; nj < 2; nj++) bOff[nj] = (uint32_t)((n0 + nj * 16 + nB) * 128);
    const uint32_t bXor = (uint32_t)((lane & 7) << 4);
    const uint32_t bCol = (lane & 8) ? 16u : 0u;

    float acc[2][4][4];
#pragma unroll
    for (int mi = 0; mi < 2; mi++)
#pragma unroll
        for (int nt = 0; nt < 4; nt++)
#pragma unroll
            for (int e = 0; e < 4; e++) acc[mi][nt][e] = 0.f;

    float ssq = 0.f;
    const uint32_t rbase = (uint32_t)(row * 128);
    const uint32_t xr = (uint32_t)((row & 7) << 4);

    for (int c = 0; c < NCH; c++) {
        const int buf = c & 1;
        // B chunk copy (pre-swizzled, L2-resident): 1024 uint4
        {
            const uint4* src = reinterpret_cast<const uint4*>(g_Wt_sw) + c * 1024;
            uint4* dst = reinterpret_cast<uint4*>(smem + SM_B + buf * 16384);
#pragma unroll
            for (int i = 0; i < 4; i++) dst[i * 256 + t] = src[i * 256 + t];
        }
        // A convert: res = ex - mean -> bf16 swizzled; ssq accumulate
        {
            unsigned char* A = smem + SM_A + buf * 8192;
            const float* mS = meanS + c * 64 + q * 16;
#pragma unroll
            for (int g = 0; g < 4; g++) {
                float4 x = cur[g];
                float4 m4 = *reinterpret_cast<const float4*>(mS + g * 4);
                float r0 = x.x - m4.x, r1 = x.y - m4.y, r2 = x.z - m4.z, r3 = x.w - m4.w;
                ssq = fmaf(r0, r0, ssq); ssq = fmaf(r1, r1, ssq);
                ssq = fmaf(r2, r2, ssq); ssq = fmaf(r3, r3, ssq);
                uint32_t off = rbase + (((uint32_t)(q * 32 + g * 8)) ^ xr);
                *reinterpret_cast<uint2*>(A + off) = make_uint2(bfx2(r0, r1), bfx2(r2, r3));
            }
        }
        // prefetch next chunk (overlaps compute via double buffer)
        if (c + 1 < NCH) {
#pragma unroll
            for (int g = 0; g < 4; g++) cur[g] = exp4[(c + 1) * 16 + g];
        }
        __syncthreads();

        const uint32_t A = sb + SM_A + buf * 8192;
        const uint32_t B = sb + SM_B + buf * 16384;
#pragma unroll
        for (int ks = 0; ks < 4; ks++) {
            const uint32_t kb = (uint32_t)(ks * 32);
            uint32_t a[2][4], b4[2][4];
#pragma unroll
            for (int mi = 0; mi < 2; mi++)
                LDMX4(a[mi], A + aOff[mi] + ((aCol + kb) ^ aXor[mi]));
#pragma unroll
            for (int nj = 0; nj < 2; nj++)
                LDMX4(b4[nj], B + bOff[nj] + ((bCol + kb) ^ bXor));
#pragma unroll
            for (int mi = 0; mi < 2; mi++)
#pragma unroll
                for (int nt = 0; nt < 4; nt++)
                    MMA16816(acc[mi][nt], a[mi], b4[nt >> 1][2 * (nt & 1)], b4[nt >> 1][2 * (nt & 1) + 1]);
        }
    }

    // ssq: reduce 4 threads per row
    ssq += __shfl_xor_sync(0xffffffffu, ssq, 1);
    ssq += __shfl_xor_sync(0xffffffffu, ssq, 2);
    float* ssqS = reinterpret_cast<float*>(smem + SM_RED);
    if ((lane & 3) == 0) ssqS[wid * 8 + (lane >> 2)] = ssq;
    __syncthreads();   // all mainloop smem reads done; safe to overwrite with Y/Minv

    // ---- epilogue: stage Y bf16 (pitch 272), copy Minv bf16 (pitch 272) ----
#pragma unroll
    for (int mi = 0; mi < 2; mi++)
#pragma unroll
        for (int nt = 0; nt < 4; nt++) {
            int m = m0 + mi * 16 + (lane >> 2);
            int n = n0 + nt * 8 + 2 * (lane & 3);
            *reinterpret_cast<uint32_t*>(smem + SM_Y + m * 272 + n * 2) =
                bfx2(acc[mi][nt][0], acc[mi][nt][1]);
            *reinterpret_cast<uint32_t*>(smem + SM_Y + (m + 8) * 272 + n * 2) =
                bfx2(acc[mi][nt][2], acc[mi][nt][3]);
        }
    {
        const uint4* msrc = reinterpret_cast<const uint4*>(g_Minv_bf);
#pragma unroll
        for (int i = 0; i < 8; i++) {
            int idx = i * 256 + t;
            int r = idx >> 4, cc = idx & 15;
            *reinterpret_cast<uint4*>(smem + SM_MI + r * 272 + cc * 16) = msrc[idx];
        }
    }
    __syncthreads();

    // ---- second GEMM: Q = Y(64x128) @ Minv(128x128), tiles as before ----
    float acc2[2][4][4];
#pragma unroll
    for (int mi = 0; mi < 2; mi++)
#pragma unroll
        for (int nt = 0; nt < 4; nt++)
#pragma unroll
            for (int e = 0; e < 4; e++) acc2[mi][nt][e] = 0.f;

    uint32_t yRow[2], miRow[2];
#pragma unroll
    for (int mi = 0; mi < 2; mi++)
        yRow[mi] = (uint32_t)(SM_Y + (m0 + mi * 16 + rA) * 272) + aCol;
#pragma unroll
    for (int nj = 0; nj < 2; nj++)
        miRow[nj] = (uint32_t)(SM_MI + (n0 + nj * 16 + nB) * 272) + bCol;

#pragma unroll
    for (int ks = 0; ks < 8; ks++) {
        const uint32_t kb = (uint32_t)(ks * 32);
        uint32_t a[2][4], b4[2][4];
#pragma unroll
        for (int mi = 0; mi < 2; mi++) LDMX4(a[mi], sb + yRow[mi] + kb);
#pragma unroll
        for (int nj = 0; nj < 2; nj++) LDMX4(b4[nj], sb + miRow[nj] + kb);
#pragma unroll
        for (int mi = 0; mi < 2; mi++)
#pragma unroll
            for (int nt = 0; nt < 4; nt++)
                MMA16816(acc2[mi][nt], a[mi], b4[nt >> 1][2 * (nt & 1)], b4[nt >> 1][2 * (nt & 1) + 1]);
    }

    // ---- dot[m] = sum_j Y[m][j] * Q[m][j]  (reload Y frags, elementwise) ----
    float* dotS = ssqS + 64;     // [4][64]
#pragma unroll
    for (int mi = 0; mi < 2; mi++) {
        float dd0 = 0.f, dd1 = 0.f;
#pragma unroll
        for (int jc = 0; jc < 2; jc++) {
            uint32_t ya[4];
            LDMX4(ya, sb + yRow[mi] + (uint32_t)(n0 * 2 + jc * 32));
#pragma unroll
            for (int h = 0; h < 2; h++) {
                int nt = jc * 2 + h;
                float2 y0 = ubfx2(ya[h * 2 + 0]);
                float2 y1 = ubfx2(ya[h * 2 + 1]);
                dd0 += acc2[mi][nt][0] * y0.x + acc2[mi][nt][1] * y0.y;
                dd1 += acc2[mi][nt][2] * y1.x + acc2[mi][nt][3] * y1.y;
            }
        }
        dd0 += __shfl_xor_sync(0xffffffffu, dd0, 1);
        dd0 += __shfl_xor_sync(0xffffffffu, dd0, 2);
        dd1 += __shfl_xor_sync(0xffffffffu, dd1, 1);
        dd1 += __shfl_xor_sync(0xffffffffu, dd1, 2);
        if ((lane & 3) == 0) {
            int m = m0 + mi * 16 + (lane >> 2);
            dotS[wn * 64 + m] = dd0;
            dotS[wn * 64 + m + 8] = dd1;
        }
    }
    __syncthreads();

    if (t < MBLK) {
        float dot = dotS[t] + dotS[64 + t] + dotS[128 + t] + dotS[192 + t];
        float c0 = g_consts[0], is2 = g_consts[1];
        out[blockIdx.x * MBLK + t] = -0.5f * (c0 + (ssqS[t] - dot) * is2);
    }
}

// ---------------- launch ----------------
extern "C" void kernel_launch(void* const* d_in, const int* in_sizes, int n_in,
                              void* d_out, int out_size) {
    const float* ex = nullptr;
    const float* W = nullptr;
    const float* lv = nullptr;
    const float* mean = nullptr;
    for (int t = 0; t < n_in; t++) {
        if (in_sizes[t] == BATCH * N_FEAT)      ex   = (const float*)d_in[t];
        else if (in_sizes[t] == N_FEAT * K_LAT) W    = (const float*)d_in[t];
        else if (in_sizes[t] == N_FEAT)         mean = (const float*)d_in[t];
        else if (in_sizes[t] == 1)              lv   = (const float*)d_in[t];
    }
    float* out = (float*)d_out;

    cudaFuncSetAttribute(k_main, cudaFuncAttributeMaxDynamicSharedMemorySize, SM_TOTAL);

    k_prep<<<NCH, 256>>>(W);
    k_gram2<<<NCH, 256>>>(W);
    k_invert<<<1, 1024>>>(lv);
    k_main<<<NBLOCKS, 256, SM_TOTAL>>>(ex, mean, out);
}

// round 10
// speedup vs baseline: 2.1073x; 1.2235x over previous
#include <cuda_runtime.h>
#include <cuda_bf16.h>
#include <cstdint>
#include <cstddef>

#define N_FEAT 3072
#define K_LAT  128
#define BATCH  8192
#define CH     64
#define NCH    48          /* 3072 / 64 */
#define MBLK   64
#define GBLK   4           /* gram blocks, 12 chunks each */

// ---------------- device scratch (static — no allocations) ----------------
__device__ float g_Mpart4[GBLK * K_LAT * K_LAT];                    // 256 KB gram partials
__device__ float g_consts[2];                                       // [0]=n log2pi+logdetC, [1]=1/sigma^2
__device__ int   g_flag;                                            // Minv-ready flag
__device__ __align__(16) __nv_bfloat16 g_Wt_sw[NCH * K_LAT * CH];   // 768 KB, per-chunk SW128 W^T
__device__ __align__(16) __nv_bfloat16 g_Minv_bf[K_LAT * K_LAT];    // 32 KB, row-major bf16 Minv

static __device__ __forceinline__ uint32_t smem_u32(const void* p) {
    uint32_t a;
    asm("{ .reg .u64 t; cvta.to.shared.u64 t, %1; cvt.u32.u64 %0, t; }" : "=r"(a) : "l"(p));
    return a;
}

#define LDMX4(r, addr) \
    asm volatile("ldmatrix.sync.aligned.m8n8.x4.shared.b16 {%0,%1,%2,%3}, [%4];" \
        : "=r"((r)[0]), "=r"((r)[1]), "=r"((r)[2]), "=r"((r)[3]) : "r"(addr))

#define MMA16816(d, a, b0, b1) \
    asm volatile("mma.sync.aligned.m16n8k16.row.col.f32.bf16.bf16.f32 " \
        "{%0,%1,%2,%3}, {%4,%5,%6,%7}, {%8,%9}, {%0,%1,%2,%3};" \
        : "+f"((d)[0]), "+f"((d)[1]), "+f"((d)[2]), "+f"((d)[3]) \
        : "r"((a)[0]), "r"((a)[1]), "r"((a)[2]), "r"((a)[3]), "r"(b0), "r"(b1))

static __device__ __forceinline__ uint32_t bfx2(float a, float b) {
    __nv_bfloat162 h = __floats2bfloat162_rn(a, b);
    return *reinterpret_cast<uint32_t*>(&h);
}
static __device__ __forceinline__ float2 ubfx2(uint32_t v) {
    float2 r;
    r.x = __uint_as_float(v << 16);
    r.y = __uint_as_float(v & 0xffff0000u);
    return r;
}
// packed f32x2 (compiles under compute_103; verified round 2)
static __device__ __forceinline__ unsigned long long pk2(float x, float y) {
    unsigned long long r;
    asm("mov.b64 %0, {%1,%2};" : "=l"(r) : "f"(x), "f"(y));
    return r;
}
static __device__ __forceinline__ float2 upk2(unsigned long long v) {
    float2 r;
    asm("mov.b64 {%0,%1}, %2;" : "=f"(r.x), "=f"(r.y) : "l"(v));
    return r;
}
static __device__ __forceinline__ unsigned long long ffma2(
    unsigned long long a, unsigned long long b, unsigned long long c) {
    unsigned long long d;
    asm("fma.rn.f32x2 %0, %1, %2, %3;" : "=l"(d) : "l"(a), "l"(b), "l"(c));
    return d;
}

// ============ k_gram: build SW128 bf16 W^T chunks + MMA gram partials ============
// grid GBLK=4, 512 threads. Block b handles chunks 12b..12b+11; partial M in fp32.
__global__ __launch_bounds__(512) void k_gram(const float* __restrict__ W) {
    __shared__ __align__(16) unsigned char buf[K_LAT * CH * 2];   // 16 KB, one chunk
    const int t = threadIdx.x, lane = t & 31, wid = t >> 5;
    const int b = blockIdx.x;
    const int wm = wid & 3, wn = wid >> 2;
    const int m0 = wm * 32, n0 = wn * 32;
    const int rA = lane & 15, cA16 = lane >> 4;
    uint32_t aOff[2], aXor[2];
#pragma unroll
    for (int mi = 0; mi < 2; mi++) {
        int r = m0 + mi * 16 + rA;
        aOff[mi] = (uint32_t)(r * 128);
        aXor[mi] = (uint32_t)((r & 7) << 4);
    }
    const uint32_t aCol = (uint32_t)(cA16 * 16);
    const int nB = (lane & 7) + ((lane & 16) ? 8 : 0);
    uint32_t bOff[2];
#pragma unroll
    for (int nj = 0; nj < 2; nj++) bOff[nj] = (uint32_t)((n0 + nj * 16 + nB) * 128);
    const uint32_t bXor = (uint32_t)((lane & 7) << 4);
    const uint32_t bCol = (lane & 8) ? 16u : 0u;
    const uint32_t base = smem_u32(buf);

    float acc[2][4][4];
#pragma unroll
    for (int mi = 0; mi < 2; mi++)
#pragma unroll
        for (int nt = 0; nt < 4; nt++)
#pragma unroll
            for (int e = 0; e < 4; e++) acc[mi][nt][e] = 0.f;

    // register prefetch of chunk 0
    float vreg[16];
    {
        const float* src = W + (size_t)(b * 12) * CH * K_LAT;
#pragma unroll
        for (int it = 0; it < 16; it++) vreg[it] = src[it * 512 + t];
    }

    for (int cc = 0; cc < 12; cc++) {
        const int ch = b * 12 + cc;
        // STS swizzled bf16 (from vreg)
#pragma unroll
        for (int it = 0; it < 16; it++) {
            int l = it * 512 + t;
            int rr = l >> 7, n = l & 127;
            unsigned off = (unsigned)(n * 128 + ((rr * 2) ^ ((n & 7) << 4)));
            *reinterpret_cast<__nv_bfloat16*>(&buf[off]) = __float2bfloat16(vreg[it]);
        }
        __syncthreads();
        // prefetch next chunk
        if (cc + 1 < 12) {
            const float* src = W + (size_t)(ch + 1) * CH * K_LAT;
#pragma unroll
            for (int it = 0; it < 16; it++) vreg[it] = src[it * 512 + t];
        }
        // persist tile for k_main
        {
            const uint4* s4 = reinterpret_cast<const uint4*>(buf);
            uint4* d4 = reinterpret_cast<uint4*>(g_Wt_sw) + ch * 1024;
            d4[t] = s4[t];
            d4[512 + t] = s4[512 + t];
        }
        // MMA: partial += Wt_chunk @ Wt_chunk^T
#pragma unroll
        for (int ks = 0; ks < 4; ks++) {
            const uint32_t kb = (uint32_t)(ks * 32);
            uint32_t a[2][4], b4[2][4];
#pragma unroll
            for (int mi = 0; mi < 2; mi++)
                LDMX4(a[mi], base + aOff[mi] + ((aCol + kb) ^ aXor[mi]));
#pragma unroll
            for (int nj = 0; nj < 2; nj++)
                LDMX4(b4[nj], base + bOff[nj] + ((bCol + kb) ^ bXor));
#pragma unroll
            for (int mi = 0; mi < 2; mi++)
#pragma unroll
                for (int nt = 0; nt < 4; nt++)
                    MMA16816(acc[mi][nt], a[mi], b4[nt >> 1][2 * (nt & 1)], b4[nt >> 1][2 * (nt & 1) + 1]);
        }
        __syncthreads();
    }
    // write fp32 partial
    float* outp = g_Mpart4 + b * (K_LAT * K_LAT);
#pragma unroll
    for (int mi = 0; mi < 2; mi++)
#pragma unroll
        for (int nt = 0; nt < 4; nt++) {
            int m = m0 + mi * 16 + (lane >> 2);
            int n = n0 + nt * 8 + 2 * (lane & 3);
            outp[m * K_LAT + n]     = acc[mi][nt][0];
            outp[m * K_LAT + n + 1] = acc[mi][nt][1];
            outp[(m + 8) * K_LAT + n]     = acc[mi][nt][2];
            outp[(m + 8) * K_LAT + n + 1] = acc[mi][nt][3];
        }
}

// ============ k_main: block 0 = reduce+GJ invert; blocks 1..128 = mainloop ============
// mainloop smem: A 2x8KB @0, B 2x16KB @16384, mean @53248 (12KB), red @65536
// epilogue smem: Y (pitch 272, 64 rows) @0, Minv (pitch 272, 128 rows) @17408
#define SM_A     0
#define SM_B     16384
#define SM_MEAN  53248
#define SM_RED   65536
#define SM_Y     0
#define SM_MI    17408
#define SM_TOTAL 66816

__global__ void __launch_bounds__(512, 1) k_main(const float* __restrict__ ex,
                                                 const float* __restrict__ mean,
                                                 const float* __restrict__ lv,
                                                 float* __restrict__ out) {
    extern __shared__ __align__(16) unsigned char smem[];
    uint32_t sb = smem_u32(smem);
    const int t = threadIdx.x, lane = t & 31, wid = t >> 5;

    if (blockIdx.x == 0) {
        // ---------- inverter block ----------
        unsigned long long* rowb = reinterpret_cast<unsigned long long*>(smem);     // [2][64]
        float* colb = reinterpret_cast<float*>(smem + 1024);                         // [2][128]
        float* pivS = reinterpret_cast<float*>(smem + 2048);                         // [128]
        float* redS = reinterpret_cast<float*>(smem + 2560);                         // [4]
        const int i = t & 127, cB = t >> 7;   // thread owns row i, cols 32cB..32cB+31
        float lv0 = lv[0];

        float a[32];
#pragma unroll
        for (int u = 0; u < 32; u++) a[u] = 0.f;
#pragma unroll
        for (int p = 0; p < GBLK; p++) {
            const float4* src = reinterpret_cast<const float4*>(
                g_Mpart4 + p * (K_LAT * K_LAT) + i * K_LAT + cB * 32);
#pragma unroll
            for (int q = 0; q < 8; q++) {
                float4 v = src[q];
                a[q * 4 + 0] += v.x; a[q * 4 + 1] += v.y;
                a[q * 4 + 2] += v.z; a[q * 4 + 3] += v.w;
            }
        }
        float sig2 = expf(lv0);
        if ((i >> 5) == cB) a[i & 31] += sig2;

        unsigned long long A2[16];
#pragma unroll
        for (int u = 0; u < 16; u++) A2[u] = pk2(a[2 * u], a[2 * u + 1]);

        int buf = 0;
        for (int k = 0; k < 128; k++) {
            if (i == k) {
#pragma unroll
                for (int u = 0; u < 16; u++) rowb[buf * 64 + cB * 16 + u] = A2[u];
            }
            if (cB == (k >> 5)) {
                int u = k & 31;
                float2 pr = upk2(A2[u >> 1]);
                colb[buf * 128 + i] = (u & 1) ? pr.y : pr.x;
            }
            __syncthreads();
            float p = colb[buf * 128 + k];
            float d = 1.0f / p;
            if (t == 0) pivS[k] = p;
            if (i == k) {
#pragma unroll
                for (int u = 0; u < 16; u++) {
                    float2 v = upk2(A2[u]);
                    A2[u] = pk2(v.x * d, v.y * d);
                }
                if (cB == (k >> 5)) {
                    int u = k & 31;
                    float2 v = upk2(A2[u >> 1]);
                    if (u & 1) v.y = d; else v.x = d;
                    A2[u >> 1] = pk2(v.x, v.y);
                }
            } else {
                float nci = -colb[buf * 128 + i] * d;
                unsigned long long n2 = pk2(nci, nci);
#pragma unroll
                for (int u = 0; u < 16; u++)
                    A2[u] = ffma2(n2, rowb[buf * 64 + cB * 16 + u], A2[u]);
                if (cB == (k >> 5)) {
                    int u = k & 31;
                    float2 v = upk2(A2[u >> 1]);
                    if (u & 1) v.y = nci; else v.x = nci;
                    A2[u >> 1] = pk2(v.x, v.y);
                }
            }
            buf ^= 1;
        }
        // emit bf16 Minv (row-major)
        {
            uint32_t* dst = reinterpret_cast<uint32_t*>(g_Minv_bf) + (i * K_LAT + cB * 32) / 2;
#pragma unroll
            for (int u = 0; u < 16; u++) {
                float2 v = upk2(A2[u]);
                dst[u] = bfx2(v.x, v.y);
            }
        }
        __syncthreads();
        // logdet in parallel
        float ld = 0.f;
        if (t < 128) ld = logf(pivS[t]);
#pragma unroll
        for (int off = 16; off > 0; off >>= 1) ld += __shfl_xor_sync(0xffffffffu, ld, off);
        if (t < 128 && (lane == 0)) redS[t >> 5] = ld;
        __syncthreads();
        if (t == 0) {
            const float LOG2PI = 1.8378770664093453f;
            float logdet = redS[0] + redS[1] + redS[2] + redS[3];
            g_consts[0] = (float)N_FEAT * LOG2PI + (float)(N_FEAT - K_LAT) * lv0 + logdet;
            g_consts[1] = expf(-lv0);
        }
        __syncthreads();
        __threadfence();
        if (t == 0)
            asm volatile("st.global.release.gpu.b32 [%0], %1;" :: "l"(&g_flag), "r"(1) : "memory");
        return;
    }

    // ---------- mainloop blocks (bid 1..128) ----------
    const int wm = wid & 3, wn = wid >> 2;       // 4 (M) x 4 (N) warps
    const int m0 = wm * 16, n0 = wn * 32;

    float* meanS = reinterpret_cast<float*>(smem + SM_MEAN);
    for (int i = t; i < N_FEAT; i += 512) meanS[i] = mean[i];

    // residual load geometry: 8 threads per row, 8 floats each
    const int row = t >> 3, q = t & 7;
    const float4* exp4 =
        reinterpret_cast<const float4*>(ex + (size_t)((blockIdx.x - 1) * MBLK + row) * N_FEAT) + q * 2;

    // ldmatrix geometry
    const int rA = lane & 15, cA16 = lane >> 4;
    const uint32_t aOff = (uint32_t)((m0 + rA) * 128);
    const uint32_t aXor = (uint32_t)(((m0 + rA) & 7) << 4);
    const uint32_t aCol = (uint32_t)(cA16 * 16);
    const int nB = (lane & 7) + ((lane & 16) ? 8 : 0);
    uint32_t bOff[2];
#pragma unroll
    for (int nj = 0; nj < 2; nj++) bOff[nj] = (uint32_t)((n0 + nj * 16 + nB) * 128);
    const uint32_t bXor = (uint32_t)((lane & 7) << 4);
    const uint32_t bCol = (lane & 8) ? 16u : 0u;

    float acc[4][4];
#pragma unroll
    for (int nt = 0; nt < 4; nt++)
#pragma unroll
        for (int e = 0; e < 4; e++) acc[nt][e] = 0.f;

    float ssq = 0.f;
    const uint32_t xr = (uint32_t)((row & 7) << 4);

    // register prefetch of chunk 0 (A residuals + B tile)
    float4 cur[2];
    uint4 bcur[2];
#pragma unroll
    for (int g = 0; g < 2; g++) cur[g] = exp4[g];
    {
        const uint4* src = reinterpret_cast<const uint4*>(g_Wt_sw);
        bcur[0] = src[t]; bcur[1] = src[512 + t];
    }

    for (int c = 0; c < NCH; c++) {
        const int buf = c & 1;
        // B STS (from registers)
        {
            uint4* dst = reinterpret_cast<uint4*>(smem + SM_B + buf * 16384);
            dst[t] = bcur[0]; dst[512 + t] = bcur[1];
        }
        // A convert: res = ex - mean -> bf16 swizzled; ssq
        {
            unsigned char* A = smem + SM_A + buf * 8192;
            const float* mS = meanS + c * 64 + q * 8;
#pragma unroll
            for (int g = 0; g < 2; g++) {
                float4 x = cur[g];
                float4 m4 = *reinterpret_cast<const float4*>(mS + g * 4);
                float r0 = x.x - m4.x, r1 = x.y - m4.y, r2 = x.z - m4.z, r3 = x.w - m4.w;
                ssq = fmaf(r0, r0, ssq); ssq = fmaf(r1, r1, ssq);
                ssq = fmaf(r2, r2, ssq); ssq = fmaf(r3, r3, ssq);
                uint32_t off = (uint32_t)(row * 128) + (((uint32_t)(q * 16 + g * 8)) ^ xr);
                *reinterpret_cast<uint2*>(A + off) = make_uint2(bfx2(r0, r1), bfx2(r2, r3));
            }
        }
        // prefetch next chunk into registers
        if (c + 1 < NCH) {
#pragma unroll
            for (int g = 0; g < 2; g++) cur[g] = exp4[(c + 1) * 16 + g];
            const uint4* src = reinterpret_cast<const uint4*>(g_Wt_sw) + (c + 1) * 1024;
            bcur[0] = src[t]; bcur[1] = src[512 + t];
        }
        __syncthreads();

        const uint32_t A = sb + SM_A + buf * 8192;
        const uint32_t B = sb + SM_B + buf * 16384;
#pragma unroll
        for (int ks = 0; ks < 4; ks++) {
            const uint32_t kb = (uint32_t)(ks * 32);
            uint32_t a[4], b4[2][4];
            LDMX4(a, A + aOff + ((aCol + kb) ^ aXor));
#pragma unroll
            for (int nj = 0; nj < 2; nj++)
                LDMX4(b4[nj], B + bOff[nj] + ((bCol + kb) ^ bXor));
#pragma unroll
            for (int nt = 0; nt < 4; nt++)
                MMA16816(acc[nt], a, b4[nt >> 1][2 * (nt & 1)], b4[nt >> 1][2 * (nt & 1) + 1]);
        }
    }
    __syncthreads();   // MMA smem reads done before Y/Minv overwrite

    // ssq: reduce 8 threads per row
    ssq += __shfl_xor_sync(0xffffffffu, ssq, 1);
    ssq += __shfl_xor_sync(0xffffffffu, ssq, 2);
    ssq += __shfl_xor_sync(0xffffffffu, ssq, 4);
    float* ssqS = reinterpret_cast<float*>(smem + SM_RED);
    float* dotS = ssqS + 64;    // [4][64]
    if ((lane & 7) == 0) ssqS[row] = ssq;

    // stage Y bf16 (pitch 272)
#pragma unroll
    for (int nt = 0; nt < 4; nt++) {
        int m = m0 + (lane >> 2);
        int n = n0 + nt * 8 + 2 * (lane & 3);
        *reinterpret_cast<uint32_t*>(smem + SM_Y + m * 272 + n * 2) = bfx2(acc[nt][0], acc[nt][1]);
        *reinterpret_cast<uint32_t*>(smem + SM_Y + (m + 8) * 272 + n * 2) = bfx2(acc[nt][2], acc[nt][3]);
    }
    // wait for Minv (block 0); usually already done
    if (t == 0) {
        unsigned f;
        do {
            asm volatile("ld.global.acquire.gpu.b32 %0, [%1];" : "=r"(f) : "l"(&g_flag) : "memory");
            if (!f) __nanosleep(64);
        } while (!f);
    }
    __syncthreads();
    // copy Minv (pitch 272)
    {
        const uint4* msrc = reinterpret_cast<const uint4*>(g_Minv_bf);
#pragma unroll
        for (int i = 0; i < 4; i++) {
            int idx = i * 512 + t;
            int r = idx >> 4, cc = idx & 15;
            *reinterpret_cast<uint4*>(smem + SM_MI + r * 272 + cc * 16) = msrc[idx];
        }
    }
    __syncthreads();

    // second GEMM: Q = Y(64x128) @ Minv(128x128)
    float acc2[4][4];
#pragma unroll
    for (int nt = 0; nt < 4; nt++)
#pragma unroll
        for (int e = 0; e < 4; e++) acc2[nt][e] = 0.f;

    const uint32_t yRow = (uint32_t)(SM_Y + (m0 + rA) * 272) + aCol;
    uint32_t miRow[2];
#pragma unroll
    for (int nj = 0; nj < 2; nj++)
        miRow[nj] = (uint32_t)(SM_MI + (n0 + nj * 16 + nB) * 272) + bCol;

#pragma unroll
    for (int ks = 0; ks < 8; ks++) {
        const uint32_t kb = (uint32_t)(ks * 32);
        uint32_t a[4], b4[2][4];
        LDMX4(a, sb + yRow + kb);
#pragma unroll
        for (int nj = 0; nj < 2; nj++) LDMX4(b4[nj], sb + miRow[nj] + kb);
#pragma unroll
        for (int nt = 0; nt < 4; nt++)
            MMA16816(acc2[nt], a, b4[nt >> 1][2 * (nt & 1)], b4[nt >> 1][2 * (nt & 1) + 1]);
    }

    // dot[m] = sum_n Y[m][n] * Q[m][n] over this warp's 32 n-cols
    // NOTE: read Y with full A-frag addressing (yRow INCLUDES the per-lane
    // (lane>>4)*16 column-split term — removing it was the R9 bug).
    {
        float dd0 = 0.f, dd1 = 0.f;
#pragma unroll
        for (int jc = 0; jc < 2; jc++) {
            uint32_t ya[4];
            LDMX4(ya, sb + yRow + (uint32_t)(n0 * 2 + jc * 32));
#pragma unroll
            for (int h = 0; h < 2; h++) {
                int nt = jc * 2 + h;
                float2 y0 = ubfx2(ya[h * 2 + 0]);
                float2 y1 = ubfx2(ya[h * 2 + 1]);
                dd0 += acc2[nt][0] * y0.x + acc2[nt][1] * y0.y;
                dd1 += acc2[nt][2] * y1.x + acc2[nt][3] * y1.y;
            }
        }
        dd0 += __shfl_xor_sync(0xffffffffu, dd0, 1);
        dd0 += __shfl_xor_sync(0xffffffffu, dd0, 2);
        dd1 += __shfl_xor_sync(0xffffffffu, dd1, 1);
        dd1 += __shfl_xor_sync(0xffffffffu, dd1, 2);
        if ((lane & 3) == 0) {
            int m = m0 + (lane >> 2);
            dotS[wn * 64 + m] = dd0;
            dotS[wn * 64 + m + 8] = dd1;
        }
    }
    __syncthreads();

    if (t < MBLK) {
        float dot = dotS[t] + dotS[64 + t] + dotS[128 + t] + dotS[192 + t];
        float c0 = g_consts[0], is2 = g_consts[1];
        out[(blockIdx.x - 1) * MBLK + t] = -0.5f * (c0 + (ssqS[t] - dot) * is2);
    }
}

// ---------------- launch ----------------
extern "C" void kernel_launch(void* const* d_in, const int* in_sizes, int n_in,
                              void* d_out, int out_size) {
    const float* ex = nullptr;
    const float* W = nullptr;
    const float* lv = nullptr;
    const float* mean = nullptr;
    for (int t = 0; t < n_in; t++) {
        if (in_sizes[t] == BATCH * N_FEAT)      ex   = (const float*)d_in[t];
        else if (in_sizes[t] == N_FEAT * K_LAT) W    = (const float*)d_in[t];
        else if (in_sizes[t] == N_FEAT)         mean = (const float*)d_in[t];
        else if (in_sizes[t] == 1)              lv   = (const float*)d_in[t];
    }
    float* out = (float*)d_out;

    cudaFuncSetAttribute(k_main, cudaFuncAttributeMaxDynamicSharedMemorySize, SM_TOTAL);

    k_gram<<<GBLK, 512>>>(W);
    k_main<<<BATCH / MBLK + 1, 512, SM_TOTAL>>>(ex, mean, lv, out);
}